// round 6
// baseline (speedup 1.0000x reference)
#include <cuda_runtime.h>
#include <math.h>
#include <stdint.h>

#define T_STEPS 160
#define BATCH   640
#define FDIM    40
#define HDIM    768
#define PJDIM   256
#define NLAYERS 3
#define NBLK    120

#define NCH0    19
#define NCH12   32
#define K0      296
#define K12     512

// ---------------- device globals ----------------------------------------------
__device__ float g_c[NLAYERS][HDIM * BATCH];   // c_perm[gcol*640+row]
__device__ float g_m[NLAYERS][HDIM * BATCH];   // m_perm[gcol*640+row]
__device__ float g_h[NLAYERS][BATCH * PJDIM];  // row-major [row][256]
__device__ unsigned g_bar_count;
__device__ unsigned g_bar_gen;

// Pre-swizzled tf32 weights: gmem order == smem order (cp.async friendly).
// Gates chunk = 4096 words: word = s*2048 + col*8 + q*2 + hi  (col 0..255 gate-interleaved)
__device__ uint32_t g_W0pre[12 * NCH0  * 4096];
__device__ uint32_t g_W1pre[12 * NCH12 * 4096];
__device__ uint32_t g_W2pre[12 * NCH12 * 4096];
// Proj chunk = 1024 words: word = s*512 + col*8 + q*2 + hi (col 0..63)
__device__ uint32_t g_Ppre [3 * 4 * 48 * 1024];

__device__ __forceinline__ float sigf(float x) { return 1.0f / (1.0f + __expf(-x)); }

__device__ __forceinline__ uint32_t f2tf32(float f) {
    uint32_t r; asm("cvt.rna.tf32.f32 %0, %1;" : "=r"(r) : "f"(f)); return r;
}

__device__ __forceinline__ void mma_tf32(float& c0, float& c1, float& c2, float& c3,
                                         uint32_t a0, uint32_t a1, uint32_t a2, uint32_t a3,
                                         uint32_t b0, uint32_t b1) {
    asm("mma.sync.aligned.m16n8k8.row.col.f32.tf32.tf32.f32 "
        "{%0,%1,%2,%3},{%4,%5,%6,%7},{%8,%9},{%0,%1,%2,%3};"
        : "+f"(c0), "+f"(c1), "+f"(c2), "+f"(c3)
        : "r"(a0), "r"(a1), "r"(a2), "r"(a3), "r"(b0), "r"(b1));
}

__device__ __forceinline__ void cp16(uint32_t dst, const void* src) {
    asm volatile("cp.async.cg.shared.global [%0], [%1], 16;" :: "r"(dst), "l"(src));
}
#define CP_COMMIT() asm volatile("cp.async.commit_group;")
#define CP_WAIT0()  asm volatile("cp.async.wait_group 0;" ::: "memory")

__device__ __forceinline__ void grid_barrier() {
    __syncthreads();
    if (threadIdx.x == 0) {
        __threadfence();
        unsigned gen = *(volatile unsigned*)&g_bar_gen;
        if (atomicAdd(&g_bar_count, 1u) == NBLK - 1) {
            g_bar_count = 0;
            __threadfence();
            atomicAdd(&g_bar_gen, 1u);
        } else {
            while (*(volatile unsigned*)&g_bar_gen == gen) { __nanosleep(64); }
        }
        __threadfence();
    }
    __syncthreads();
}

// ---------------- weight precompute --------------------------------------------
// dst[idx]: idx = nt*(NCH*4096) + ch*4096 + gidx*4 + w
// gidx = s*512 + col*2 + g2 ; q = 2*g2 + (w>>1), hi = w&1 ; kk = s*8+q+4*hi
__device__ void prep_w(uint32_t* dst, const float* W, long idx, int NCH, int K) {
    int nt = (int)(idx / ((long)NCH * 4096));
    int r  = (int)(idx % ((long)NCH * 4096));
    int ch = r / 4096;
    int r2 = r % 4096;
    int gidx = r2 >> 2, w = r2 & 3;
    int s = gidx >> 9, col = (gidx >> 1) & 255, g2 = gidx & 1;
    int q = g2 * 2 + (w >> 1), hi = w & 1;
    int k = ch * 16 + s * 8 + q + hi * 4;
    int gate = col & 3, cc = col >> 2;
    float v = (k < K) ? W[k * (4 * HDIM) + gate * HDIM + nt * 64 + cc] : 0.0f;
    dst[idx] = f2tf32(v);
}

__global__ void precompute_weights(const float* __restrict__ W0, const float* __restrict__ W1,
                                   const float* __restrict__ W2, const float* __restrict__ P0,
                                   const float* __restrict__ P1, const float* __restrict__ P2)
{
    long idx = (long)blockIdx.x * 256 + threadIdx.x;
    const long NW0  = 12L * NCH0  * 4096;
    const long NW12 = 12L * NCH12 * 4096;
    if (idx < NW0)  { prep_w(g_W0pre, W0, idx, NCH0, K0);  return; }
    idx -= NW0;
    if (idx < NW12) { prep_w(g_W1pre, W1, idx, NCH12, K12); return; }
    idx -= NW12;
    if (idx < NW12) { prep_w(g_W2pre, W2, idx, NCH12, K12); return; }
    idx -= NW12;
    if (idx < 3L * 4 * 48 * 1024) {
        int save = (int)idx;
        int layer = (int)(idx / (4 * 48 * 1024));
        int r  = (int)(idx % (4 * 48 * 1024));
        int nt4 = r / (48 * 1024);
        int r2  = r % (48 * 1024);
        int ch  = r2 / 1024;
        int r3  = r2 % 1024;
        int gidx = r3 >> 2, w = r3 & 3;
        int s = gidx >> 7, col = (gidx >> 1) & 63, g2 = gidx & 1;
        int q = g2 * 2 + (w >> 1), hi = w & 1;
        int k = ch * 16 + s * 8 + q + hi * 4;
        const float* P = (layer == 0) ? P0 : (layer == 1) ? P1 : P2;
        g_Ppre[save] = f2tf32(P[k * PJDIM + nt4 * 64 + col]);
    }
}

// ---------------- gates: 64x256 tile + fused cell update -----------------------
// smem: sA[2][1024] (word = s*512 + row*8 + q*2 + hi), sW[2][4096] at word 2048.
template <int XK, int NCH, bool XCONST>
__device__ void gates_mma(const float* __restrict__ xA,
                          const float* __restrict__ hA,
                          const uint32_t* __restrict__ Wlayer,
                          const float* __restrict__ bias,
                          float* __restrict__ cbuf, float* __restrict__ mbuf,
                          uint32_t* __restrict__ sm, uint32_t sb)
{
    constexpr int K = XK + PJDIM;
    const int tid = threadIdx.x, lane = tid & 31, wid = tid >> 5;
    const int bid = blockIdx.x;
    const int m0  = (bid % 10) * 64;
    const int nt0 = bid / 10;
    const uint32_t* Wp = Wlayer + (size_t)nt0 * NCH * 4096;
    const int wm = wid >> 2, wn = wid & 3;
    const int grp = lane >> 2, q = lane & 3;
    const int arow = tid >> 2, aj = tid & 3;

    float acc[2][8][4];
#pragma unroll
    for (int mt = 0; mt < 2; mt++)
#pragma unroll
        for (int nt = 0; nt < 8; nt++)
#pragma unroll
            for (int r = 0; r < 4; r++) acc[mt][nt][r] = 0.0f;

    float4 ra;

    auto ldA = [&](int ch) {
        int kg = ch * 16 + aj * 4;
        if (kg < XK) {
            ra = XCONST ? __ldg((const float4*)&xA[(m0 + arow) * XK + kg])
                        : __ldcg((const float4*)&xA[(m0 + arow) * XK + kg]);
        } else if (kg < K) {
            ra = __ldcg((const float4*)&hA[(m0 + arow) * PJDIM + (kg - XK)]);
        } else {
            ra = make_float4(0.f, 0.f, 0.f, 0.f);
        }
    };
    auto stA = [&](int buf) {
        uint32_t* d = sm + buf * 1024 + (aj >> 1) * 512 + arow * 8 + (aj & 1);
        d[0] = f2tf32(ra.x); d[2] = f2tf32(ra.y);
        d[4] = f2tf32(ra.z); d[6] = f2tf32(ra.w);
    };
    auto ldW = [&](int ch, int buf) {
        const uint32_t* src = Wp + (size_t)ch * 4096 + tid * 4;
        uint32_t dst = sb + (2048 + buf * 4096 + tid * 4) * 4;
#pragma unroll
        for (int e = 0; e < 4; e++)
            cp16(dst + e * 4096, src + e * 1024);
        CP_COMMIT();
    };

    ldW(0, 0);
    ldA(0);
    stA(0);
    CP_WAIT0();
    __syncthreads();

    for (int ch = 0; ch < NCH; ch++) {
        int buf = ch & 1;
        bool more = (ch + 1 < NCH);
        if (more) { ldW(ch + 1, buf ^ 1); ldA(ch + 1); }

        const uint32_t* bA = sm + buf * 1024;
        const uint32_t* bW = sm + 2048 + buf * 4096;
#pragma unroll
        for (int s = 0; s < 2; s++) {
            uint2 a02[2], a13[2];
#pragma unroll
            for (int mt = 0; mt < 2; mt++) {
                int r = wm * 32 + mt * 16 + grp;
                a02[mt] = *(const uint2*)&bA[s * 512 + r * 8 + q * 2];
                a13[mt] = *(const uint2*)&bA[s * 512 + (r + 8) * 8 + q * 2];
            }
#pragma unroll
            for (int nt = 0; nt < 8; nt++) {
                int col = wn * 64 + nt * 8 + grp;
                uint2 b01 = *(const uint2*)&bW[s * 2048 + col * 8 + q * 2];
#pragma unroll
                for (int mt = 0; mt < 2; mt++)
                    mma_tf32(acc[mt][nt][0], acc[mt][nt][1], acc[mt][nt][2], acc[mt][nt][3],
                             a02[mt].x, a13[mt].x, a02[mt].y, a13[mt].y, b01.x, b01.y);
            }
        }
        if (more) stA(buf ^ 1);
        CP_WAIT0();
        __syncthreads();
    }

    // Epilogue (unchanged from R4): lane pair assembles (i,j,f,o).
    const int gc0 = nt0 * 64;
    const int p = lane & 1;
#pragma unroll
    for (int nt = 0; nt < 8; nt++) {
        int cc = wn * 16 + 2 * nt + (q >> 1);
        int gc = gc0 + cc;
        float bi = __ldg(&bias[gc]);
        float bj = __ldg(&bias[gc + HDIM]);
        float bf = __ldg(&bias[gc + 2 * HDIM]);
        float bo = __ldg(&bias[gc + 3 * HDIM]);
#pragma unroll
        for (int mt = 0; mt < 2; mt++) {
            float c0 = acc[mt][nt][0], c1 = acc[mt][nt][1];
            float c2 = acc[mt][nt][2], c3 = acc[mt][nt][3];
            float v = __shfl_xor_sync(0xffffffffu, p ? c0 : c2, 1);
            float w = __shfl_xor_sync(0xffffffffu, p ? c1 : c3, 1);
            float zi, zj, zf, zo;
            if (p == 0) { zi = c0; zj = c1; zf = v;  zo = w;  }
            else        { zi = v;  zj = w;  zf = c2; zo = c3; }
            int row = m0 + wm * 32 + mt * 16 + grp + (p ? 8 : 0);
            zi += bi; zj += bj; zf += bf; zo += bo;
            float cold = cbuf[gc * BATCH + row];
            float cn = sigf(zf + 1.0f) * cold + sigf(zi) * tanhf(zj);
            float mm = sigf(zo) * tanhf(cn);
            cbuf[gc * BATCH + row] = cn;
            mbuf[gc * BATCH + row] = mm;
        }
    }
}

// ---------------- projection: one 64x64 tile per block -------------------------
__device__ void proj_mma(const float* __restrict__ mperm,
                         const uint32_t* __restrict__ Pblk,  // per (layer, nt4)
                         float* __restrict__ hout,
                         int m0, int nt4,
                         uint32_t* __restrict__ sm, uint32_t sb)
{
    const int tid = threadIdx.x, lane = tid & 31, wid = tid >> 5;
    const int wm = wid >> 2, wn = wid & 3;
    const int grp = lane >> 2, q = lane & 3;
    const int klocal = tid >> 4;           // 0..15
    const int row4 = (tid & 15) * 4;

    float acc[2][2][4];
#pragma unroll
    for (int mt = 0; mt < 2; mt++)
#pragma unroll
        for (int nt = 0; nt < 2; nt++)
#pragma unroll
            for (int r = 0; r < 4; r++) acc[mt][nt][r] = 0.0f;

    float4 ra;
    auto ldA = [&](int ch) {
        ra = __ldcg((const float4*)&mperm[(ch * 16 + klocal) * BATCH + m0 + row4]);
    };
    auto stA = [&](int buf) {
        int s = klocal >> 3, qq = klocal & 3, hi = (klocal >> 2) & 1;
        uint32_t* d = sm + buf * 1024 + s * 512 + row4 * 8 + qq * 2 + hi;
        d[0] = f2tf32(ra.x); d[8] = f2tf32(ra.y);
        d[16] = f2tf32(ra.z); d[24] = f2tf32(ra.w);
    };
    auto ldW = [&](int ch, int buf) {
        const uint32_t* src = Pblk + (size_t)ch * 1024 + tid * 4;
        uint32_t dst = sb + (2048 + buf * 1024 + tid * 4) * 4;
        cp16(dst, src);
        CP_COMMIT();
    };

    ldW(0, 0);
    ldA(0);
    stA(0);
    CP_WAIT0();
    __syncthreads();

    for (int ch = 0; ch < 48; ch++) {
        int buf = ch & 1;
        bool more = (ch + 1 < 48);
        if (more) { ldW(ch + 1, buf ^ 1); ldA(ch + 1); }

        const uint32_t* bA = sm + buf * 1024;
        const uint32_t* bW = sm + 2048 + buf * 1024;
#pragma unroll
        for (int s = 0; s < 2; s++) {
            uint2 a02[2], a13[2];
#pragma unroll
            for (int mt = 0; mt < 2; mt++) {
                int r = wm * 32 + mt * 16 + grp;
                a02[mt] = *(const uint2*)&bA[s * 512 + r * 8 + q * 2];
                a13[mt] = *(const uint2*)&bA[s * 512 + (r + 8) * 8 + q * 2];
            }
#pragma unroll
            for (int nt = 0; nt < 2; nt++) {
                int col = wn * 16 + nt * 8 + grp;
                uint2 b01 = *(const uint2*)&bW[s * 512 + col * 8 + q * 2];
#pragma unroll
                for (int mt = 0; mt < 2; mt++)
                    mma_tf32(acc[mt][nt][0], acc[mt][nt][1], acc[mt][nt][2], acc[mt][nt][3],
                             a02[mt].x, a13[mt].x, a02[mt].y, a13[mt].y, b01.x, b01.y);
            }
        }
        if (more) stA(buf ^ 1);
        CP_WAIT0();
        __syncthreads();
    }

#pragma unroll
    for (int mt = 0; mt < 2; mt++)
#pragma unroll
        for (int nt = 0; nt < 2; nt++) {
            int row = m0 + wm * 32 + mt * 16 + grp;
            int col = nt4 * 64 + wn * 16 + nt * 8 + 2 * q;
            *(float2*)&hout[row * PJDIM + col] =
                make_float2(acc[mt][nt][0], acc[mt][nt][1]);
            *(float2*)&hout[(row + 8) * PJDIM + col] =
                make_float2(acc[mt][nt][2], acc[mt][nt][3]);
        }
}

// ---------------- persistent driver --------------------------------------------
__global__ void __launch_bounds__(256, 1)
lstm_persistent(const float* __restrict__ x,
                const float* __restrict__ b0, const float* __restrict__ b1,
                const float* __restrict__ b2,
                float* __restrict__ out)
{
    extern __shared__ uint32_t dynsmem[];   // sA[2][1024] + sW[2][4096] = 10240 words
    __shared__ float red[8];
    uint32_t* sm = dynsmem;
    uint32_t sb = (uint32_t)__cvta_generic_to_shared(dynsmem);

    const int bid = blockIdx.x;
    const int tid = threadIdx.x;

    for (int i = bid * 256 + tid; i < NLAYERS * HDIM * BATCH; i += NBLK * 256)
        ((float*)g_c)[i] = 0.0f;
    for (int i = bid * 256 + tid; i < NLAYERS * BATCH * PJDIM; i += NBLK * 256)
        ((float*)g_h)[i] = 0.0f;
    grid_barrier();

    const int p_layer = bid / 40;
    const int p_rem   = bid % 40;
    const int p_m0    = (p_rem % 10) * 64;
    const int p_nt4   = p_rem / 10;
    const uint32_t* Pblk = g_Ppre + ((size_t)p_layer * 4 + p_nt4) * 48 * 1024;

    for (int s = 0; s < T_STEPS + 2; s++) {
        // phase A: gates wavefront (layer l at time s-l)
        if (s < T_STEPS)
            gates_mma<FDIM, NCH0, true>(x + (size_t)s * BATCH * FDIM, g_h[0],
                                        g_W0pre, b0, g_c[0], g_m[0], sm, sb);
        if (s >= 1 && s - 1 < T_STEPS)
            gates_mma<PJDIM, NCH12, false>(g_h[0], g_h[1], g_W1pre, b1,
                                           g_c[1], g_m[1], sm, sb);
        if (s >= 2 && s - 2 < T_STEPS)
            gates_mma<PJDIM, NCH12, false>(g_h[1], g_h[2], g_W2pre, b2,
                                           g_c[2], g_m[2], sm, sb);
        grid_barrier();

        // phase B: one 64x64 proj tile per block
        if (s - p_layer >= 0 && s - p_layer < T_STEPS)
            proj_mma(g_m[p_layer], Pblk, g_h[p_layer], p_m0, p_nt4, sm, sb);
        grid_barrier();
    }

    for (int b = bid; b < BATCH; b += NBLK) {
        float v = __ldcg(&g_h[NLAYERS - 1][b * PJDIM + tid]);
        float sm2 = v * v;
#pragma unroll
        for (int o = 16; o > 0; o >>= 1) sm2 += __shfl_xor_sync(0xffffffffu, sm2, o);
        if ((tid & 31) == 0) red[tid >> 5] = sm2;
        __syncthreads();
        float tot = red[0] + red[1] + red[2] + red[3] +
                    red[4] + red[5] + red[6] + red[7];
        out[b * PJDIM + tid] = v * rsqrtf(fmaxf(tot, 1e-12f));
        __syncthreads();
    }
}

extern "C" void kernel_launch(void* const* d_in, const int* in_sizes, int n_in,
                              void* d_out, int out_size)
{
    const float* x  = (const float*)d_in[0];
    const float* W0 = (const float*)d_in[1];
    const float* b0 = (const float*)d_in[2];
    const float* P0 = (const float*)d_in[3];
    const float* W1 = (const float*)d_in[4];
    const float* b1 = (const float*)d_in[5];
    const float* P1 = (const float*)d_in[6];
    const float* W2 = (const float*)d_in[7];
    const float* b2 = (const float*)d_in[8];
    const float* P2 = (const float*)d_in[9];
    float* out = (float*)d_out;
    (void)in_sizes; (void)n_in; (void)out_size;

    // words: 12*19*4096 + 2*12*32*4096 + 3*4*48*1024 = 4,669,440 -> 18240 blocks
    precompute_weights<<<18240, 256>>>(W0, W1, W2, P0, P1, P2);
    lstm_persistent<<<NBLK, 256, 40960>>>(x, b0, b1, b2, out);
}

// round 7
// speedup vs baseline: 1.0015x; 1.0015x over previous
#include <cuda_runtime.h>
#include <math.h>
#include <stdint.h>

#define T_STEPS 160
#define BATCH   640
#define FDIM    40
#define HDIM    768
#define PJDIM   256
#define NLAYERS 3
#define NBLK    120

#define NCH0    19
#define NCH12   32
#define K0      296
#define K12     512

// ---------------- device globals ----------------------------------------------
__device__ float g_c[NLAYERS][HDIM * BATCH];   // c_perm[gcol*640+row]
__device__ float g_m[NLAYERS][HDIM * BATCH];   // m_perm[gcol*640+row]
__device__ float g_h[NLAYERS][BATCH * PJDIM];  // row-major [row][256]
__device__ unsigned g_bar_count;
__device__ unsigned g_bar_gen;

// Pre-swizzled tf32 weights: gmem order == smem order (cp.async friendly).
// Gates chunk = 4096 words: word = s*2048 + col*8 + q*2 + hi  (col 0..255 gate-interleaved)
__device__ uint32_t g_W0pre[12 * NCH0  * 4096];
__device__ uint32_t g_W1pre[12 * NCH12 * 4096];
__device__ uint32_t g_W2pre[12 * NCH12 * 4096];
// Proj chunk = 1024 words: word = s*512 + col*8 + q*2 + hi (col 0..63)
__device__ uint32_t g_Ppre [3 * 4 * 48 * 1024];

__device__ __forceinline__ float sigf(float x) { return 1.0f / (1.0f + __expf(-x)); }

__device__ __forceinline__ uint32_t f2tf32(float f) {
    uint32_t r; asm("cvt.rna.tf32.f32 %0, %1;" : "=r"(r) : "f"(f)); return r;
}

__device__ __forceinline__ void mma_tf32(float& c0, float& c1, float& c2, float& c3,
                                         uint32_t a0, uint32_t a1, uint32_t a2, uint32_t a3,
                                         uint32_t b0, uint32_t b1) {
    asm("mma.sync.aligned.m16n8k8.row.col.f32.tf32.tf32.f32 "
        "{%0,%1,%2,%3},{%4,%5,%6,%7},{%8,%9},{%0,%1,%2,%3};"
        : "+f"(c0), "+f"(c1), "+f"(c2), "+f"(c3)
        : "r"(a0), "r"(a1), "r"(a2), "r"(a3), "r"(b0), "r"(b1));
}

__device__ __forceinline__ void cp16(uint32_t dst, const void* src) {
    asm volatile("cp.async.cg.shared.global [%0], [%1], 16;" :: "r"(dst), "l"(src));
}
#define CP_COMMIT() asm volatile("cp.async.commit_group;")
#define CP_WAIT0()  asm volatile("cp.async.wait_group 0;" ::: "memory")

__device__ __forceinline__ void grid_barrier() {
    __syncthreads();
    if (threadIdx.x == 0) {
        __threadfence();
        unsigned gen = *(volatile unsigned*)&g_bar_gen;
        if (atomicAdd(&g_bar_count, 1u) == NBLK - 1) {
            g_bar_count = 0;
            __threadfence();
            atomicAdd(&g_bar_gen, 1u);
        } else {
            while (*(volatile unsigned*)&g_bar_gen == gen) { __nanosleep(64); }
        }
        __threadfence();
    }
    __syncthreads();
}

// ---------------- weight precompute --------------------------------------------
// dst[idx]: idx = nt*(NCH*4096) + ch*4096 + gidx*4 + w
// gidx = s*512 + col*2 + g2 ; q = 2*g2 + (w>>1), hi = w&1 ; kk = s*8+q+4*hi
__device__ void prep_w(uint32_t* dst, const float* W, long idx, int NCH, int K) {
    int nt = (int)(idx / ((long)NCH * 4096));
    int r  = (int)(idx % ((long)NCH * 4096));
    int ch = r / 4096;
    int r2 = r % 4096;
    int gidx = r2 >> 2, w = r2 & 3;
    int s = gidx >> 9, col = (gidx >> 1) & 255, g2 = gidx & 1;
    int q = g2 * 2 + (w >> 1), hi = w & 1;
    int k = ch * 16 + s * 8 + q + hi * 4;
    int gate = col & 3, cc = col >> 2;
    float v = (k < K) ? W[k * (4 * HDIM) + gate * HDIM + nt * 64 + cc] : 0.0f;
    dst[idx] = f2tf32(v);
}

__global__ void precompute_weights(const float* __restrict__ W0, const float* __restrict__ W1,
                                   const float* __restrict__ W2, const float* __restrict__ P0,
                                   const float* __restrict__ P1, const float* __restrict__ P2)
{
    long idx = (long)blockIdx.x * 256 + threadIdx.x;
    const long NW0  = 12L * NCH0  * 4096;
    const long NW12 = 12L * NCH12 * 4096;
    if (idx < NW0)  { prep_w(g_W0pre, W0, idx, NCH0, K0);  return; }
    idx -= NW0;
    if (idx < NW12) { prep_w(g_W1pre, W1, idx, NCH12, K12); return; }
    idx -= NW12;
    if (idx < NW12) { prep_w(g_W2pre, W2, idx, NCH12, K12); return; }
    idx -= NW12;
    if (idx < 3L * 4 * 48 * 1024) {
        int save = (int)idx;
        int layer = (int)(idx / (4 * 48 * 1024));
        int r  = (int)(idx % (4 * 48 * 1024));
        int nt4 = r / (48 * 1024);
        int r2  = r % (48 * 1024);
        int ch  = r2 / 1024;
        int r3  = r2 % 1024;
        int gidx = r3 >> 2, w = r3 & 3;
        int s = gidx >> 7, col = (gidx >> 1) & 63, g2 = gidx & 1;
        int q = g2 * 2 + (w >> 1), hi = w & 1;
        int k = ch * 16 + s * 8 + q + hi * 4;
        const float* P = (layer == 0) ? P0 : (layer == 1) ? P1 : P2;
        g_Ppre[save] = f2tf32(P[k * PJDIM + nt4 * 64 + col]);
    }
}

// ---------------- gates: 64x256 tile + fused cell update -----------------------
// smem: sA[2][1024] (word = s*512 + row*8 + q*2 + hi), sW[2][4096] at word 2048.
template <int XK, int NCH, bool XCONST>
__device__ void gates_mma(const float* __restrict__ xA,
                          const float* __restrict__ hA,
                          const uint32_t* __restrict__ Wlayer,
                          const float* __restrict__ bias,
                          float* __restrict__ cbuf, float* __restrict__ mbuf,
                          uint32_t* __restrict__ sm, uint32_t sb)
{
    constexpr int K = XK + PJDIM;
    const int tid = threadIdx.x, lane = tid & 31, wid = tid >> 5;
    const int bid = blockIdx.x;
    const int m0  = (bid % 10) * 64;
    const int nt0 = bid / 10;
    const uint32_t* Wp = Wlayer + (size_t)nt0 * NCH * 4096;
    const int wm = wid >> 2, wn = wid & 3;
    const int grp = lane >> 2, q = lane & 3;
    const int arow = tid >> 2, aj = tid & 3;

    float acc[2][8][4];
#pragma unroll
    for (int mt = 0; mt < 2; mt++)
#pragma unroll
        for (int nt = 0; nt < 8; nt++)
#pragma unroll
            for (int r = 0; r < 4; r++) acc[mt][nt][r] = 0.0f;

    float4 ra;

    auto ldA = [&](int ch) {
        int kg = ch * 16 + aj * 4;
        if (kg < XK) {
            ra = XCONST ? __ldg((const float4*)&xA[(m0 + arow) * XK + kg])
                        : __ldcg((const float4*)&xA[(m0 + arow) * XK + kg]);
        } else if (kg < K) {
            ra = __ldcg((const float4*)&hA[(m0 + arow) * PJDIM + (kg - XK)]);
        } else {
            ra = make_float4(0.f, 0.f, 0.f, 0.f);
        }
    };
    auto stA = [&](int buf) {
        uint32_t* d = sm + buf * 1024 + (aj >> 1) * 512 + arow * 8 + (aj & 1);
        d[0] = f2tf32(ra.x); d[2] = f2tf32(ra.y);
        d[4] = f2tf32(ra.z); d[6] = f2tf32(ra.w);
    };
    auto ldW = [&](int ch, int buf) {
        const uint32_t* src = Wp + (size_t)ch * 4096 + tid * 4;
        uint32_t dst = sb + (2048 + buf * 4096 + tid * 4) * 4;
#pragma unroll
        for (int e = 0; e < 4; e++)
            cp16(dst + e * 4096, src + e * 1024);
        CP_COMMIT();
    };

    ldW(0, 0);
    ldA(0);
    stA(0);
    CP_WAIT0();
    __syncthreads();

    for (int ch = 0; ch < NCH; ch++) {
        int buf = ch & 1;
        bool more = (ch + 1 < NCH);
        if (more) { ldW(ch + 1, buf ^ 1); ldA(ch + 1); }

        const uint32_t* bA = sm + buf * 1024;
        const uint32_t* bW = sm + 2048 + buf * 4096;
#pragma unroll
        for (int s = 0; s < 2; s++) {
            uint2 a02[2], a13[2];
#pragma unroll
            for (int mt = 0; mt < 2; mt++) {
                int r = wm * 32 + mt * 16 + grp;
                a02[mt] = *(const uint2*)&bA[s * 512 + r * 8 + q * 2];
                a13[mt] = *(const uint2*)&bA[s * 512 + (r + 8) * 8 + q * 2];
            }
#pragma unroll
            for (int nt = 0; nt < 8; nt++) {
                int col = wn * 64 + nt * 8 + grp;
                uint2 b01 = *(const uint2*)&bW[s * 2048 + col * 8 + q * 2];
#pragma unroll
                for (int mt = 0; mt < 2; mt++)
                    mma_tf32(acc[mt][nt][0], acc[mt][nt][1], acc[mt][nt][2], acc[mt][nt][3],
                             a02[mt].x, a13[mt].x, a02[mt].y, a13[mt].y, b01.x, b01.y);
            }
        }
        if (more) stA(buf ^ 1);
        CP_WAIT0();
        __syncthreads();
    }

    // Epilogue (unchanged from R4): lane pair assembles (i,j,f,o).
    const int gc0 = nt0 * 64;
    const int p = lane & 1;
#pragma unroll
    for (int nt = 0; nt < 8; nt++) {
        int cc = wn * 16 + 2 * nt + (q >> 1);
        int gc = gc0 + cc;
        float bi = __ldg(&bias[gc]);
        float bj = __ldg(&bias[gc + HDIM]);
        float bf = __ldg(&bias[gc + 2 * HDIM]);
        float bo = __ldg(&bias[gc + 3 * HDIM]);
#pragma unroll
        for (int mt = 0; mt < 2; mt++) {
            float c0 = acc[mt][nt][0], c1 = acc[mt][nt][1];
            float c2 = acc[mt][nt][2], c3 = acc[mt][nt][3];
            float v = __shfl_xor_sync(0xffffffffu, p ? c0 : c2, 1);
            float w = __shfl_xor_sync(0xffffffffu, p ? c1 : c3, 1);
            float zi, zj, zf, zo;
            if (p == 0) { zi = c0; zj = c1; zf = v;  zo = w;  }
            else        { zi = v;  zj = w;  zf = c2; zo = c3; }
            int row = m0 + wm * 32 + mt * 16 + grp + (p ? 8 : 0);
            zi += bi; zj += bj; zf += bf; zo += bo;
            float cold = cbuf[gc * BATCH + row];
            float cn = sigf(zf + 1.0f) * cold + sigf(zi) * tanhf(zj);
            float mm = sigf(zo) * tanhf(cn);
            cbuf[gc * BATCH + row] = cn;
            mbuf[gc * BATCH + row] = mm;
        }
    }
}

// ---------------- projection: one 64x64 tile per block -------------------------
__device__ void proj_mma(const float* __restrict__ mperm,
                         const uint32_t* __restrict__ Pblk,  // per (layer, nt4)
                         float* __restrict__ hout,
                         int m0, int nt4,
                         uint32_t* __restrict__ sm, uint32_t sb)
{
    const int tid = threadIdx.x, lane = tid & 31, wid = tid >> 5;
    const int wm = wid >> 2, wn = wid & 3;
    const int grp = lane >> 2, q = lane & 3;
    const int klocal = tid >> 4;           // 0..15
    const int row4 = (tid & 15) * 4;

    float acc[2][2][4];
#pragma unroll
    for (int mt = 0; mt < 2; mt++)
#pragma unroll
        for (int nt = 0; nt < 2; nt++)
#pragma unroll
            for (int r = 0; r < 4; r++) acc[mt][nt][r] = 0.0f;

    float4 ra;
    auto ldA = [&](int ch) {
        ra = __ldcg((const float4*)&mperm[(ch * 16 + klocal) * BATCH + m0 + row4]);
    };
    auto stA = [&](int buf) {
        int s = klocal >> 3, qq = klocal & 3, hi = (klocal >> 2) & 1;
        uint32_t* d = sm + buf * 1024 + s * 512 + row4 * 8 + qq * 2 + hi;
        d[0] = f2tf32(ra.x); d[8] = f2tf32(ra.y);
        d[16] = f2tf32(ra.z); d[24] = f2tf32(ra.w);
    };
    auto ldW = [&](int ch, int buf) {
        const uint32_t* src = Pblk + (size_t)ch * 1024 + tid * 4;
        uint32_t dst = sb + (2048 + buf * 1024 + tid * 4) * 4;
        cp16(dst, src);
        CP_COMMIT();
    };

    ldW(0, 0);
    ldA(0);
    stA(0);
    CP_WAIT0();
    __syncthreads();

    for (int ch = 0; ch < 48; ch++) {
        int buf = ch & 1;
        bool more = (ch + 1 < 48);
        if (more) { ldW(ch + 1, buf ^ 1); ldA(ch + 1); }

        const uint32_t* bA = sm + buf * 1024;
        const uint32_t* bW = sm + 2048 + buf * 1024;
#pragma unroll
        for (int s = 0; s < 2; s++) {
            uint2 a02[2], a13[2];
#pragma unroll
            for (int mt = 0; mt < 2; mt++) {
                int r = wm * 32 + mt * 16 + grp;
                a02[mt] = *(const uint2*)&bA[s * 512 + r * 8 + q * 2];
                a13[mt] = *(const uint2*)&bA[s * 512 + (r + 8) * 8 + q * 2];
            }
#pragma unroll
            for (int nt = 0; nt < 2; nt++) {
                int col = wn * 16 + nt * 8 + grp;
                uint2 b01 = *(const uint2*)&bW[s * 512 + col * 8 + q * 2];
#pragma unroll
                for (int mt = 0; mt < 2; mt++)
                    mma_tf32(acc[mt][nt][0], acc[mt][nt][1], acc[mt][nt][2], acc[mt][nt][3],
                             a02[mt].x, a13[mt].x, a02[mt].y, a13[mt].y, b01.x, b01.y);
            }
        }
        if (more) stA(buf ^ 1);
        CP_WAIT0();
        __syncthreads();
    }

#pragma unroll
    for (int mt = 0; mt < 2; mt++)
#pragma unroll
        for (int nt = 0; nt < 2; nt++) {
            int row = m0 + wm * 32 + mt * 16 + grp;
            int col = nt4 * 64 + wn * 16 + nt * 8 + 2 * q;
            *(float2*)&hout[row * PJDIM + col] =
                make_float2(acc[mt][nt][0], acc[mt][nt][1]);
            *(float2*)&hout[(row + 8) * PJDIM + col] =
                make_float2(acc[mt][nt][2], acc[mt][nt][3]);
        }
}

// ---------------- persistent driver --------------------------------------------
__global__ void __launch_bounds__(256, 1)
lstm_persistent(const float* __restrict__ x,
                const float* __restrict__ b0, const float* __restrict__ b1,
                const float* __restrict__ b2,
                float* __restrict__ out)
{
    extern __shared__ uint32_t dynsmem[];   // sA[2][1024] + sW[2][4096] = 10240 words
    __shared__ float red[8];
    uint32_t* sm = dynsmem;
    uint32_t sb = (uint32_t)__cvta_generic_to_shared(dynsmem);

    const int bid = blockIdx.x;
    const int tid = threadIdx.x;

    for (int i = bid * 256 + tid; i < NLAYERS * HDIM * BATCH; i += NBLK * 256)
        ((float*)g_c)[i] = 0.0f;
    for (int i = bid * 256 + tid; i < NLAYERS * BATCH * PJDIM; i += NBLK * 256)
        ((float*)g_h)[i] = 0.0f;
    grid_barrier();

    const int p_layer = bid / 40;
    const int p_rem   = bid % 40;
    const int p_m0    = (p_rem % 10) * 64;
    const int p_nt4   = p_rem / 10;
    const uint32_t* Pblk = g_Ppre + ((size_t)p_layer * 4 + p_nt4) * 48 * 1024;

    for (int s = 0; s < T_STEPS + 2; s++) {
        // phase A: gates wavefront (layer l at time s-l)
        if (s < T_STEPS)
            gates_mma<FDIM, NCH0, true>(x + (size_t)s * BATCH * FDIM, g_h[0],
                                        g_W0pre, b0, g_c[0], g_m[0], sm, sb);
        if (s >= 1 && s - 1 < T_STEPS)
            gates_mma<PJDIM, NCH12, false>(g_h[0], g_h[1], g_W1pre, b1,
                                           g_c[1], g_m[1], sm, sb);
        if (s >= 2 && s - 2 < T_STEPS)
            gates_mma<PJDIM, NCH12, false>(g_h[1], g_h[2], g_W2pre, b2,
                                           g_c[2], g_m[2], sm, sb);
        grid_barrier();

        // phase B: one 64x64 proj tile per block
        if (s - p_layer >= 0 && s - p_layer < T_STEPS)
            proj_mma(g_m[p_layer], Pblk, g_h[p_layer], p_m0, p_nt4, sm, sb);
        grid_barrier();
    }

    for (int b = bid; b < BATCH; b += NBLK) {
        float v = __ldcg(&g_h[NLAYERS - 1][b * PJDIM + tid]);
        float sm2 = v * v;
#pragma unroll
        for (int o = 16; o > 0; o >>= 1) sm2 += __shfl_xor_sync(0xffffffffu, sm2, o);
        if ((tid & 31) == 0) red[tid >> 5] = sm2;
        __syncthreads();
        float tot = red[0] + red[1] + red[2] + red[3] +
                    red[4] + red[5] + red[6] + red[7];
        out[b * PJDIM + tid] = v * rsqrtf(fmaxf(tot, 1e-12f));
        __syncthreads();
    }
}

extern "C" void kernel_launch(void* const* d_in, const int* in_sizes, int n_in,
                              void* d_out, int out_size)
{
    const float* x  = (const float*)d_in[0];
    const float* W0 = (const float*)d_in[1];
    const float* b0 = (const float*)d_in[2];
    const float* P0 = (const float*)d_in[3];
    const float* W1 = (const float*)d_in[4];
    const float* b1 = (const float*)d_in[5];
    const float* P1 = (const float*)d_in[6];
    const float* W2 = (const float*)d_in[7];
    const float* b2 = (const float*)d_in[8];
    const float* P2 = (const float*)d_in[9];
    float* out = (float*)d_out;
    (void)in_sizes; (void)n_in; (void)out_size;

    // words: 12*19*4096 + 2*12*32*4096 + 3*4*48*1024 = 4,669,440 -> 18240 blocks
    precompute_weights<<<18240, 256>>>(W0, W1, W2, P0, P1, P2);
    lstm_persistent<<<NBLK, 256, 40960>>>(x, b0, b1, b2, out);
}